// round 1
// baseline (speedup 1.0000x reference)
#include <cuda_runtime.h>
#include <cstdint>
#include <cstddef>

// ---------------------------------------------------------------------------
// CQEncoder: 2-layer bidirectional GAT + gated fusion.
// B=64, Nc=1024, Nq=128, F=NHID=512, H=8, DH=64, L=2
// ---------------------------------------------------------------------------

#define NEGF (-9e15f)

static const int Bb = 64;
static const int NC = 1024;
static const int NQ = 128;
static const int FD = 512;   // F == NHID == 512
static const int HH = 8;
static const int DHD = 64;

// ------------------------- device scratch (static, no runtime alloc) -------
__device__ float g_PC[(size_t)64 * 1024 * 512];     // big projection (clip)
__device__ float g_PQ[(size_t)64 * 128 * 512];      // small projection (question)
__device__ float g_agg[(size_t)64 * 1024 * 512];    // q_agg / c_agg
__device__ float g_NA[(size_t)64 * 1024 * 512];     // fusion new_a
__device__ float g_FP[(size_t)64 * 1024 * 512];     // fusion gate pre-activation
__device__ float g_clipA[(size_t)64 * 1024 * 512];  // layer-0 clip_new
__device__ float g_questA[(size_t)64 * 128 * 512];  // layer-0 question_new
__device__ float g_ea[(size_t)64 * 8 * 1024];
__device__ float g_eb[(size_t)64 * 8 * 1024];
__device__ float g_cmax[(size_t)64 * 8 * 1024];
__device__ float g_cinv[(size_t)64 * 8 * 1024];
__device__ float g_Wt[512 * 512];
__device__ float g_Wt2[512 * 512];
__device__ int   g_adjT1[(size_t)64 * 128 * 1024];  // clip2questionadj transposed: [B, Nq, Nc]
__device__ int   g_adjT2[(size_t)64 * 1024 * 128];  // question2clipadj transposed: [B, Nc, Nq]

// ---------------------------------------------------------------------------
// GEMM: C[M,512] (+)= A[M,512] @ B[512,512], fp32, row-major.
// 128x128 tile, BK=16, 256 threads, 8x8 per-thread micro tile.
// ---------------------------------------------------------------------------
template <int BETA>
__global__ __launch_bounds__(256) void gemm512_kernel(
    const float* __restrict__ A, const float* __restrict__ Bm,
    float* __restrict__ C, int M)
{
    __shared__ float As[16][128];
    __shared__ float Bs[16][128];

    const int n0 = blockIdx.x * 128;
    const int m0 = blockIdx.y * 128;
    const int tid = threadIdx.x;
    const int tn = tid & 15;
    const int tm = tid >> 4;

    const int arow = tid >> 2;          // 0..63 (plus +64)
    const int acol = (tid & 3) * 4;     // k offset within 16
    const int brow = tid >> 5;          // 0..7 (plus +8)
    const int bcol = (tid & 31) * 4;    // n offset within 128

    float acc[8][8];
#pragma unroll
    for (int i = 0; i < 8; i++)
#pragma unroll
        for (int j = 0; j < 8; j++) acc[i][j] = 0.f;

    for (int k0 = 0; k0 < 512; k0 += 16) {
#pragma unroll
        for (int r = 0; r < 2; r++) {
            int row = arow + r * 64;
            float4 v = *(const float4*)&A[(size_t)(m0 + row) * 512 + k0 + acol];
            As[acol + 0][row] = v.x;
            As[acol + 1][row] = v.y;
            As[acol + 2][row] = v.z;
            As[acol + 3][row] = v.w;
        }
#pragma unroll
        for (int r = 0; r < 2; r++) {
            int row = brow + r * 8;
            float4 v = *(const float4*)&Bm[(size_t)(k0 + row) * 512 + n0 + bcol];
            *(float4*)&Bs[row][bcol] = v;
        }
        __syncthreads();
#pragma unroll
        for (int k = 0; k < 16; k++) {
            float a[8], b[8];
            float4 a0 = *(const float4*)&As[k][tm * 4];
            float4 a1 = *(const float4*)&As[k][64 + tm * 4];
            float4 b0 = *(const float4*)&Bs[k][tn * 4];
            float4 b1 = *(const float4*)&Bs[k][64 + tn * 4];
            a[0]=a0.x; a[1]=a0.y; a[2]=a0.z; a[3]=a0.w;
            a[4]=a1.x; a[5]=a1.y; a[6]=a1.z; a[7]=a1.w;
            b[0]=b0.x; b[1]=b0.y; b[2]=b0.z; b[3]=b0.w;
            b[4]=b1.x; b[5]=b1.y; b[6]=b1.z; b[7]=b1.w;
#pragma unroll
            for (int i = 0; i < 8; i++)
#pragma unroll
                for (int j = 0; j < 8; j++) acc[i][j] += a[i] * b[j];
        }
        __syncthreads();
    }

#pragma unroll
    for (int i = 0; i < 8; i++) {
        int row = m0 + ((i < 4) ? (tm * 4 + i) : (64 + tm * 4 + (i - 4)));
#pragma unroll
        for (int jj = 0; jj < 2; jj++) {
            int col = n0 + ((jj == 0) ? (tn * 4) : (64 + tn * 4));
            float* cp = &C[(size_t)row * 512 + col];
            float4 v;
            v.x = acc[i][jj * 4 + 0];
            v.y = acc[i][jj * 4 + 1];
            v.z = acc[i][jj * 4 + 2];
            v.w = acc[i][jj * 4 + 3];
            if (BETA) {
                float4 o = *(const float4*)cp;
                v.x += o.x; v.y += o.y; v.z += o.z; v.w += o.w;
            }
            *(float4*)cp = v;
        }
    }
}

// ---------------------------------------------------------------------------
// flatten W[H,F,DH] -> Wt[F, H*DH]  (so proj = X @ Wt)
// ---------------------------------------------------------------------------
__global__ void transposeW_kernel(const float* __restrict__ W, float* __restrict__ Wt)
{
    int idx = blockIdx.x * blockDim.x + threadIdx.x;
    if (idx >= 512 * 512) return;
    int f = idx >> 9;
    int c = idx & 511;
    int h = c >> 6;
    int d = c & 63;
    Wt[idx] = W[((size_t)h * 512 + f) * 64 + d];
}

// adj[B,N,M] -> adjT[B,M,N]
__global__ void transposeAdj_kernel(const int* __restrict__ A, int* __restrict__ At,
                                    int N, int M)
{
    int idx = blockIdx.x * blockDim.x + threadIdx.x;
    int total = Bb * N * M;
    if (idx >= total) return;
    int b = idx / (N * M);
    int r = idx - b * (N * M);
    int m = r / N;
    int n = r - m * N;
    At[idx] = A[(size_t)b * N * M + (size_t)n * M + m];
}

// ---------------------------------------------------------------------------
// ehalf: out[b,h,n] = sum_d P[b,n, h*64+d] * avec[h*128 + off + d]
// one block per row (B*Nper rows), warp w handles head w.
// ---------------------------------------------------------------------------
__global__ void ehalf_kernel(const float* __restrict__ P, const float* __restrict__ avec,
                             int off, float* __restrict__ out, int Nper)
{
    int row = blockIdx.x;
    int w = threadIdx.x >> 5;
    int lane = threadIdx.x & 31;
    int b = row / Nper;
    int n = row - b * Nper;
    const float* p = P + (size_t)row * 512 + w * 64;
    const float* a = avec + w * 128 + off;
    float s = p[lane] * a[lane] + p[lane + 32] * a[lane + 32];
#pragma unroll
    for (int o = 16; o > 0; o >>= 1) s += __shfl_down_sync(0xffffffffu, s, o);
    if (lane == 0) out[((size_t)(b * HH + w)) * Nper + n] = s;
}

// ---------------------------------------------------------------------------
// column stats for softmax over the N axis (axis=2 in reference):
// for each (b, h, m): max_n / sum_n exp over masked lrelu(ea[n]+eb[m]).
// One block (128 thr) per (b, m), all 8 heads.
// ---------------------------------------------------------------------------
__global__ __launch_bounds__(128) void colstats_kernel(
    const int* __restrict__ adjT, const float* __restrict__ eaN,
    const float* __restrict__ ebM, float* __restrict__ cmax,
    float* __restrict__ cinv, int Mdim, int NRED)
{
    int bm = blockIdx.x;
    int b = bm / Mdim;
    int m = bm - b * Mdim;
    const int* arow = adjT + (size_t)bm * NRED;
    int tid = threadIdx.x;
    int lane = tid & 31, w = tid >> 5;

    float ebv[8];
#pragma unroll
    for (int h = 0; h < 8; h++) ebv[h] = ebM[((size_t)(b * 8 + h)) * Mdim + m];

    float vmax[8];
#pragma unroll
    for (int h = 0; h < 8; h++) vmax[h] = NEGF;

    for (int n = tid; n < NRED; n += 128) {
        int adjv = arow[n];
#pragma unroll
        for (int h = 0; h < 8; h++) {
            float e = eaN[((size_t)(b * 8 + h)) * NRED + n] + ebv[h];
            e = (e >= 0.f) ? e : 0.2f * e;
            float v = (adjv > 0) ? e : NEGF;
            vmax[h] = fmaxf(vmax[h], v);
        }
    }

    __shared__ float red[8][4];
#pragma unroll
    for (int h = 0; h < 8; h++) {
        float v = vmax[h];
#pragma unroll
        for (int o = 16; o > 0; o >>= 1) v = fmaxf(v, __shfl_xor_sync(0xffffffffu, v, o));
        if (lane == 0) red[h][w] = v;
    }
    __syncthreads();
    float gmax[8];
#pragma unroll
    for (int h = 0; h < 8; h++)
        gmax[h] = fmaxf(fmaxf(red[h][0], red[h][1]), fmaxf(red[h][2], red[h][3]));
    __syncthreads();

    float vsum[8];
#pragma unroll
    for (int h = 0; h < 8; h++) vsum[h] = 0.f;
    for (int n = tid; n < NRED; n += 128) {
        int adjv = arow[n];
#pragma unroll
        for (int h = 0; h < 8; h++) {
            float e = eaN[((size_t)(b * 8 + h)) * NRED + n] + ebv[h];
            e = (e >= 0.f) ? e : 0.2f * e;
            float v = (adjv > 0) ? e : NEGF;
            vsum[h] += expf(v - gmax[h]);
        }
    }
#pragma unroll
    for (int h = 0; h < 8; h++) {
        float v = vsum[h];
#pragma unroll
        for (int o = 16; o > 0; o >>= 1) v += __shfl_xor_sync(0xffffffffu, v, o);
        if (lane == 0) red[h][w] = v;
    }
    __syncthreads();
    if (tid < 8) {
        int h = tid;
        float s = red[h][0] + red[h][1] + red[h][2] + red[h][3];
        cmax[((size_t)(b * 8 + h)) * Mdim + m] = gmax[h];
        cinv[((size_t)(b * 8 + h)) * Mdim + m] = 1.f / s;
    }
}

// ---------------------------------------------------------------------------
// Fused attention q2c: out[b, n, h*64+d] = elu( sum_m att[n,m] * Wb[m,d] )
// att generated on the fly (n tile of 64, m = 128 question nodes).
// grid: (Nc/64, B*H), 256 threads. Dynamic smem.
// ---------------------------------------------------------------------------
__global__ __launch_bounds__(256) void attn_q2c_kernel(
    const float* __restrict__ ea, const float* __restrict__ eb,
    const float* __restrict__ cmax, const float* __restrict__ cinv,
    const int* __restrict__ adj, const float* __restrict__ PQ,
    float* __restrict__ agg)
{
    extern __shared__ float sm[];
    float* eb_s = sm;                 // 128
    float* cm_s = sm + 128;           // 128
    float* ci_s = sm + 256;           // 128
    float* ea_s = sm + 384;           // 64
    float* Wb_s = sm + 448;           // 128*64
    float* att_s = sm + 448 + 8192;   // 128*68 (att[m][n], pitch 68)

    int bh = blockIdx.y;
    int b = bh >> 3;
    int h = bh & 7;
    int n0 = blockIdx.x * 64;
    int tid = threadIdx.x;

    if (tid < 128) {
        eb_s[tid] = eb[(size_t)bh * 128 + tid];
        cm_s[tid] = cmax[(size_t)bh * 128 + tid];
        ci_s[tid] = cinv[(size_t)bh * 128 + tid];
    } else if (tid < 192) {
        ea_s[tid - 128] = ea[(size_t)bh * 1024 + n0 + (tid - 128)];
    }
    for (int idx = tid; idx < 128 * 64; idx += 256) {
        int m = idx >> 6, d = idx & 63;
        Wb_s[idx] = PQ[((size_t)(b * 128 + m)) * 512 + h * 64 + d];
    }
    __syncthreads();

    for (int idx = tid; idx < 64 * 128; idx += 256) {
        int m = idx & 127, n = idx >> 7;
        int adjv = adj[((size_t)(b * 1024 + n0 + n)) * 128 + m];
        float v = ea_s[n] + eb_s[m];
        v = (v >= 0.f) ? v : 0.2f * v;
        v = (adjv > 0) ? v : NEGF;
        att_s[m * 68 + n] = expf(v - cm_s[m]) * ci_s[m];
    }
    __syncthreads();

    int tn = tid & 15, tm = tid >> 4;
    int d0 = tn * 4, nl0 = tm * 4;
    float acc[4][4];
#pragma unroll
    for (int i = 0; i < 4; i++)
#pragma unroll
        for (int j = 0; j < 4; j++) acc[i][j] = 0.f;

    for (int k = 0; k < 128; k++) {
        float4 a4 = *(const float4*)&att_s[k * 68 + nl0];
        float4 b4 = *(const float4*)&Wb_s[k * 64 + d0];
        float a[4] = {a4.x, a4.y, a4.z, a4.w};
        float bb[4] = {b4.x, b4.y, b4.z, b4.w};
#pragma unroll
        for (int i = 0; i < 4; i++)
#pragma unroll
            for (int j = 0; j < 4; j++) acc[i][j] += a[i] * bb[j];
    }

#pragma unroll
    for (int i = 0; i < 4; i++) {
#pragma unroll
        for (int j = 0; j < 4; j++) {
            float v = acc[i][j];
            v = (v > 0.f) ? v : expm1f(v);
            agg[((size_t)(b * 1024 + n0 + nl0 + i)) * 512 + h * 64 + d0 + j] = v;
        }
    }
}

// ---------------------------------------------------------------------------
// Fused attention c2q: out[b, n(0..127), h*64+d] = elu( sum_{m<1024} att[n,m]*Wb[m,d] )
// grid: B*H blocks, 256 threads, m tiled by 64. Dynamic smem.
// ---------------------------------------------------------------------------
__global__ __launch_bounds__(256) void attn_c2q_kernel(
    const float* __restrict__ ea, const float* __restrict__ eb,
    const float* __restrict__ cmax, const float* __restrict__ cinv,
    const int* __restrict__ adj, const float* __restrict__ PC,
    float* __restrict__ agg)
{
    extern __shared__ float sm[];
    float* ea_s = sm;                 // 128
    float* eb_s = sm + 128;           // 64
    float* cm_s = sm + 192;           // 64
    float* ci_s = sm + 256;           // 64
    float* Wb_s = sm + 320;           // 64*64
    float* att_s = sm + 320 + 4096;   // 64*132 (att[m][n], pitch 132)

    int bh = blockIdx.x;
    int b = bh >> 3;
    int h = bh & 7;
    int tid = threadIdx.x;

    if (tid < 128) ea_s[tid] = ea[(size_t)bh * 128 + tid];

    int tn = tid & 15, tm = tid >> 4;
    int d0 = tn * 4, nl0 = tm * 8;
    float acc[8][4];
#pragma unroll
    for (int i = 0; i < 8; i++)
#pragma unroll
        for (int j = 0; j < 4; j++) acc[i][j] = 0.f;

    for (int mt = 0; mt < 16; mt++) {
        int m0 = mt * 64;
        if (tid < 64) eb_s[tid] = eb[(size_t)bh * 1024 + m0 + tid];
        else if (tid < 128) cm_s[tid - 64] = cmax[(size_t)bh * 1024 + m0 + (tid - 64)];
        else if (tid < 192) ci_s[tid - 128] = cinv[(size_t)bh * 1024 + m0 + (tid - 128)];
        for (int idx = tid; idx < 64 * 64; idx += 256) {
            int m = idx >> 6, d = idx & 63;
            Wb_s[idx] = PC[((size_t)(b * 1024 + m0 + m)) * 512 + h * 64 + d];
        }
        __syncthreads();

        for (int idx = tid; idx < 128 * 64; idx += 256) {
            int m = idx & 63, n = idx >> 6;
            int adjv = adj[((size_t)(b * 128 + n)) * 1024 + m0 + m];
            float v = ea_s[n] + eb_s[m];
            v = (v >= 0.f) ? v : 0.2f * v;
            v = (adjv > 0) ? v : NEGF;
            att_s[m * 132 + n] = expf(v - cm_s[m]) * ci_s[m];
        }
        __syncthreads();

        for (int k = 0; k < 64; k++) {
            float4 b4 = *(const float4*)&Wb_s[k * 64 + d0];
            float4 a0 = *(const float4*)&att_s[k * 132 + nl0];
            float4 a1 = *(const float4*)&att_s[k * 132 + nl0 + 4];
            float a[8] = {a0.x, a0.y, a0.z, a0.w, a1.x, a1.y, a1.z, a1.w};
            float bb[4] = {b4.x, b4.y, b4.z, b4.w};
#pragma unroll
            for (int i = 0; i < 8; i++)
#pragma unroll
                for (int j = 0; j < 4; j++) acc[i][j] += a[i] * bb[j];
        }
        __syncthreads();
    }

#pragma unroll
    for (int i = 0; i < 8; i++) {
#pragma unroll
        for (int j = 0; j < 4; j++) {
            float v = acc[i][j];
            v = (v > 0.f) ? v : expm1f(v);
            agg[((size_t)(b * 128 + nl0 + i)) * 512 + h * 64 + d0 + j] = v;
        }
    }
}

// ---------------------------------------------------------------------------
// Fusion elementwise: out = sig(fp)*na + (1-sig(fp))*a     (float4)
// ---------------------------------------------------------------------------
__global__ void fuse_ew_kernel(const float* __restrict__ a, const float* __restrict__ na,
                               const float* __restrict__ fp, float* __restrict__ out, int n4)
{
    int i = blockIdx.x * blockDim.x + threadIdx.x;
    if (i >= n4) return;
    float4 av = ((const float4*)a)[i];
    float4 nv = ((const float4*)na)[i];
    float4 fv = ((const float4*)fp)[i];
    float4 o;
    {
        float s = 1.f / (1.f + expf(-fv.x)); o.x = s * nv.x + (1.f - s) * av.x;
    }
    {
        float s = 1.f / (1.f + expf(-fv.y)); o.y = s * nv.y + (1.f - s) * av.y;
    }
    {
        float s = 1.f / (1.f + expf(-fv.z)); o.z = s * nv.z + (1.f - s) * av.z;
    }
    {
        float s = 1.f / (1.f + expf(-fv.w)); o.w = s * nv.w + (1.f - s) * av.w;
    }
    ((float4*)out)[i] = o;
}

// ---------------------------------------------------------------------------
// host side
// ---------------------------------------------------------------------------
static float* symf(const void* sym)
{
    void* p = nullptr;
    cudaGetSymbolAddress(&p, sym);
    return (float*)p;
}
static int* symi(const void* sym)
{
    void* p = nullptr;
    cudaGetSymbolAddress(&p, sym);
    return (int*)p;
}

static void gemm(const float* A, const float* Bm, float* C, int M, int beta)
{
    dim3 grid(4, M / 128);
    if (beta)
        gemm512_kernel<1><<<grid, 256>>>(A, Bm, C, M);
    else
        gemm512_kernel<0><<<grid, 256>>>(A, Bm, C, M);
}

extern "C" void kernel_launch(void* const* d_in, const int* in_sizes, int n_in,
                              void* d_out, int out_size)
{
    const float* clip0 = (const float*)d_in[0];
    const float* quest0 = (const float*)d_in[1];
    const int* adj1 = (const int*)d_in[2];   // [B, Nc, Nq]
    const int* adj2 = (const int*)d_in[3];   // [B, Nq, Nc]
    const float* W_q2c = (const float*)d_in[4];
    const float* a_q2c = (const float*)d_in[5];
    const float* W_c2q = (const float*)d_in[6];
    const float* a_c2q = (const float*)d_in[7];
    const float* fus_q2c = (const float*)d_in[8];
    const float* fus_c2q = (const float*)d_in[9];

    float* out_clip = (float*)d_out;
    float* out_quest = out_clip + (size_t)Bb * NC * FD;

    float* pPC = symf(g_PC);
    float* pPQ = symf(g_PQ);
    float* pAgg = symf(g_agg);
    float* pNA = symf(g_NA);
    float* pFP = symf(g_FP);
    float* pClipA = symf(g_clipA);
    float* pQuestA = symf(g_questA);
    float* pEa = symf(g_ea);
    float* pEb = symf(g_eb);
    float* pCmax = symf(g_cmax);
    float* pCinv = symf(g_cinv);
    float* pWt = symf(g_Wt);
    float* pWt2 = symf(g_Wt2);
    int* pAdjT1 = symi(g_adjT1);
    int* pAdjT2 = symi(g_adjT2);

    const int SMEM_Q2C = (448 + 8192 + 128 * 68) * 4;     // 69376 B
    const int SMEM_C2Q = (320 + 4096 + 64 * 132) * 4;     // 51456 B
    cudaFuncSetAttribute(attn_q2c_kernel, cudaFuncAttributeMaxDynamicSharedMemorySize, SMEM_Q2C);
    cudaFuncSetAttribute(attn_c2q_kernel, cudaFuncAttributeMaxDynamicSharedMemorySize, SMEM_C2Q);

    // transpose adjacencies once (constant across layers)
    {
        int tot1 = Bb * NC * NQ;
        transposeAdj_kernel<<<(tot1 + 255) / 256, 256>>>(adj1, pAdjT1, NC, NQ);
        transposeAdj_kernel<<<(tot1 + 255) / 256, 256>>>(adj2, pAdjT2, NQ, NC);
    }

    const size_t MCLIP = (size_t)Bb * NC;   // 65536
    const size_t MQ = (size_t)Bb * NQ;      // 8192

    const float* curC = clip0;
    const float* curQ = quest0;

    for (int l = 0; l < 2; l++) {
        float* clipNew = (l == 1) ? out_clip : pClipA;
        float* questNew = (l == 1) ? out_quest : pQuestA;
        const float* aq = a_q2c + (size_t)l * HH * 128;
        const float* ac = a_c2q + (size_t)l * HH * 128;

        transposeW_kernel<<<(512 * 512 + 255) / 256, 256>>>(W_q2c + (size_t)l * HH * FD * DHD, pWt);
        transposeW_kernel<<<(512 * 512 + 255) / 256, 256>>>(W_c2q + (size_t)l * HH * FD * DHD, pWt2);

        // ---------------- q2c GAT ----------------
        gemm(curC, pWt, pPC, (int)MCLIP, 0);          // Wa (clip)
        gemm(curQ, pWt, pPQ, (int)MQ, 0);             // Wb (question)
        ehalf_kernel<<<(int)MCLIP, 256>>>(pPC, aq, 0, pEa, NC);
        ehalf_kernel<<<(int)MQ, 256>>>(pPQ, aq, 64, pEb, NQ);
        colstats_kernel<<<Bb * NQ, 128>>>(pAdjT1, pEa, pEb, pCmax, pCinv, NQ, NC);
        attn_q2c_kernel<<<dim3(NC / 64, Bb * HH), 256, SMEM_Q2C>>>(
            pEa, pEb, pCmax, pCinv, adj1, pPQ, pAgg);

        // ---------------- fusion (clip side) ----------------
        const float* fp = fus_q2c + (size_t)l * 4 * FD * FD;
        gemm(curC, fp + 0 * 262144, pNA, (int)MCLIP, 0);
        gemm(pAgg, fp + 1 * 262144, pNA, (int)MCLIP, 1);
        gemm(curC, fp + 2 * 262144, pFP, (int)MCLIP, 0);
        gemm(pAgg, fp + 3 * 262144, pFP, (int)MCLIP, 1);
        fuse_ew_kernel<<<(int)((MCLIP * FD / 4 + 255) / 256), 256>>>(
            curC, pNA, pFP, clipNew, (int)(MCLIP * FD / 4));

        // ---------------- c2q GAT (uses OLD clip) ----------------
        gemm(curQ, pWt2, pPQ, (int)MQ, 0);            // Wa (question)
        gemm(curC, pWt2, pPC, (int)MCLIP, 0);         // Wb (clip)
        ehalf_kernel<<<(int)MQ, 256>>>(pPQ, ac, 0, pEa, NQ);
        ehalf_kernel<<<(int)MCLIP, 256>>>(pPC, ac, 64, pEb, NC);
        colstats_kernel<<<Bb * NC, 128>>>(pAdjT2, pEa, pEb, pCmax, pCinv, NC, NQ);
        attn_c2q_kernel<<<Bb * HH, 256, SMEM_C2Q>>>(
            pEa, pEb, pCmax, pCinv, adj2, pPC, pAgg);

        // ---------------- fusion (question side) ----------------
        const float* fq = fus_c2q + (size_t)l * 4 * FD * FD;
        gemm(curQ, fq + 0 * 262144, pNA, (int)MQ, 0);
        gemm(pAgg, fq + 1 * 262144, pNA, (int)MQ, 1);
        gemm(curQ, fq + 2 * 262144, pFP, (int)MQ, 0);
        gemm(pAgg, fq + 3 * 262144, pFP, (int)MQ, 1);
        fuse_ew_kernel<<<(int)((MQ * FD / 4 + 255) / 256), 256>>>(
            curQ, pNA, pFP, questNew, (int)(MQ * FD / 4));

        curC = clipNew;
        curQ = questNew;
    }
    (void)in_sizes; (void)n_in; (void)out_size;
}

// round 6
// speedup vs baseline: 1.5593x; 1.5593x over previous
#include <cuda_runtime.h>
#include <cstdint>
#include <cstddef>

// ---------------------------------------------------------------------------
// CQEncoder: 2-layer bidirectional GAT + gated fusion.
// B=64, Nc=1024, Nq=128, F=NHID=512, H=8, DH=64, L=2
// Round 6 (= round 5 resubmit; container flake, kernel audited clean):
// dense GEMMs on mma.sync.m16n8k8 TF32 (baseline PTX ISA, compute_100-safe).
// ---------------------------------------------------------------------------

#define NEGF (-9e15f)

static const int Bb = 64;
static const int NC = 1024;
static const int NQ = 128;
static const int FD = 512;
static const int HH = 8;

// ------------------------- device scratch ----------------------------------
__device__ float g_PC[(size_t)64 * 1024 * 512];     // clip projection
__device__ float g_PQ[(size_t)64 * 128 * 512];      // question projection
__device__ float g_agg[(size_t)64 * 1024 * 512];    // q_agg / c_agg
__device__ float g_NF[(size_t)64 * 1024 * 1024];    // fusion output [M,1024]
__device__ float g_clipA[(size_t)64 * 1024 * 512];
__device__ float g_questA[(size_t)64 * 128 * 512];
__device__ float g_ea[(size_t)64 * 8 * 1024];
__device__ float g_eb[(size_t)64 * 8 * 1024];
__device__ float g_cmax[(size_t)64 * 8 * 1024];
__device__ float g_cinv[(size_t)64 * 8 * 1024];
__device__ float g_Wt[512 * 512];
__device__ float g_Wt2[512 * 512];
__device__ float g_BtFus[1024 * 1024];
__device__ int   g_adjT1[(size_t)64 * 128 * 1024];
__device__ int   g_adjT2[(size_t)64 * 1024 * 128];

__device__ __forceinline__ uint32_t cvt_tf32(float f)
{
    uint32_t r;
    asm("cvt.rna.tf32.f32 %0, %1;" : "=r"(r) : "f"(f));
    return r;
}

// ---------------------------------------------------------------------------
// TF32 mma.sync GEMM: C[M,Ntot] = [A0 | A1] @ Bm^T
//   A0/A1: [M,512] fp32 row-major (A1 used for K in [512,1024), may be null)
//   Bm:    [Ntot, KS*32] fp32 row-major (Bt layout: Bt[n,k])
//   Block tile 128x128, BK=32, 8 warps (2x4), warp tile 64x32 (4x4 m16n8k8).
//   Smem stride 36 -> conflict-free fragment loads. Reg-prefetch next k-tile.
// ---------------------------------------------------------------------------
__global__ __launch_bounds__(256) void mma_gemm_kernel(
    const float* __restrict__ A0, const float* __restrict__ A1,
    const float* __restrict__ Bm, float* __restrict__ C,
    int Ntot, int KS)
{
    __shared__ uint32_t As[128][36];
    __shared__ uint32_t Bs[128][36];

    const int tid = threadIdx.x;
    const int wid = tid >> 5;
    const int lane = tid & 31;
    const int n0 = blockIdx.x * 128;
    const int m0 = blockIdx.y * 128;
    const int wm = (wid >> 2) * 64;    // warp m offset: 0 or 64
    const int wn = (wid & 3) * 32;     // warp n offset: 0,32,64,96
    const int tg = lane >> 2;          // 0..7
    const int tr = lane & 3;           // 0..3

    const size_t ldb = (size_t)(KS * 32);

    float c[4][4][4];
#pragma unroll
    for (int mt = 0; mt < 4; mt++)
#pragma unroll
        for (int nt = 0; nt < 4; nt++)
#pragma unroll
            for (int j = 0; j < 4; j++) c[mt][nt][j] = 0.f;

    uint32_t ar[4][4], br[4][4];

    // ---- prefetch k-tile 0 into registers ----
    {
        const float* Ab = A0;
#pragma unroll
        for (int i = 0; i < 4; i++) {
            int f = tid + i * 256;
            int r = f >> 3, ck = (f & 7) << 2;
            float4 v = *(const float4*)(Ab + (size_t)(m0 + r) * 512 + ck);
            ar[i][0] = cvt_tf32(v.x); ar[i][1] = cvt_tf32(v.y);
            ar[i][2] = cvt_tf32(v.z); ar[i][3] = cvt_tf32(v.w);
            float4 w = *(const float4*)(Bm + (size_t)(n0 + r) * ldb + ck);
            br[i][0] = cvt_tf32(w.x); br[i][1] = cvt_tf32(w.y);
            br[i][2] = cvt_tf32(w.z); br[i][3] = cvt_tf32(w.w);
        }
    }

    for (int kt = 0; kt < KS; kt++) {
        // ---- store staged regs to smem ----
#pragma unroll
        for (int i = 0; i < 4; i++) {
            int f = tid + i * 256;
            int r = f >> 3, ck = (f & 7) << 2;
            As[r][ck + 0] = ar[i][0]; As[r][ck + 1] = ar[i][1];
            As[r][ck + 2] = ar[i][2]; As[r][ck + 3] = ar[i][3];
            Bs[r][ck + 0] = br[i][0]; Bs[r][ck + 1] = br[i][1];
            Bs[r][ck + 2] = br[i][2]; Bs[r][ck + 3] = br[i][3];
        }
        __syncthreads();

        // ---- prefetch next k-tile ----
        if (kt + 1 < KS) {
            const int k0 = (kt + 1) * 32;
            const float* Ab = (A1 && k0 >= 512) ? A1 : A0;
            const int ka = (A1 && k0 >= 512) ? k0 - 512 : k0;
#pragma unroll
            for (int i = 0; i < 4; i++) {
                int f = tid + i * 256;
                int r = f >> 3, ck = (f & 7) << 2;
                float4 v = *(const float4*)(Ab + (size_t)(m0 + r) * 512 + ka + ck);
                ar[i][0] = cvt_tf32(v.x); ar[i][1] = cvt_tf32(v.y);
                ar[i][2] = cvt_tf32(v.z); ar[i][3] = cvt_tf32(v.w);
                float4 w = *(const float4*)(Bm + (size_t)(n0 + r) * ldb + k0 + ck);
                br[i][0] = cvt_tf32(w.x); br[i][1] = cvt_tf32(w.y);
                br[i][2] = cvt_tf32(w.z); br[i][3] = cvt_tf32(w.w);
            }
        }

        // ---- compute 32-deep k with 4 x (m16n8k8) steps ----
#pragma unroll
        for (int kk = 0; kk < 32; kk += 8) {
            uint32_t a[4][4], b[4][2];
#pragma unroll
            for (int mt = 0; mt < 4; mt++) {
                int r0 = wm + mt * 16 + tg;
                a[mt][0] = As[r0][kk + tr];
                a[mt][1] = As[r0 + 8][kk + tr];
                a[mt][2] = As[r0][kk + tr + 4];
                a[mt][3] = As[r0 + 8][kk + tr + 4];
            }
#pragma unroll
            for (int nt = 0; nt < 4; nt++) {
                int r0 = wn + nt * 8 + tg;
                b[nt][0] = Bs[r0][kk + tr];
                b[nt][1] = Bs[r0][kk + tr + 4];
            }
#pragma unroll
            for (int mt = 0; mt < 4; mt++)
#pragma unroll
                for (int nt = 0; nt < 4; nt++) {
                    asm volatile(
                        "mma.sync.aligned.m16n8k8.row.col.f32.tf32.tf32.f32 "
                        "{%0,%1,%2,%3}, {%4,%5,%6,%7}, {%8,%9}, {%0,%1,%2,%3};"
                        : "+f"(c[mt][nt][0]), "+f"(c[mt][nt][1]),
                          "+f"(c[mt][nt][2]), "+f"(c[mt][nt][3])
                        : "r"(a[mt][0]), "r"(a[mt][1]), "r"(a[mt][2]), "r"(a[mt][3]),
                          "r"(b[nt][0]), "r"(b[nt][1]));
                }
        }
        __syncthreads();
    }

    // ---- epilogue ----
#pragma unroll
    for (int mt = 0; mt < 4; mt++) {
        int rrow = m0 + wm + mt * 16 + tg;
#pragma unroll
        for (int nt = 0; nt < 4; nt++) {
            int ccol = n0 + wn + nt * 8 + tr * 2;
            float2 v0 = make_float2(c[mt][nt][0], c[mt][nt][1]);
            float2 v1 = make_float2(c[mt][nt][2], c[mt][nt][3]);
            *(float2*)&C[(size_t)rrow * Ntot + ccol] = v0;
            *(float2*)&C[(size_t)(rrow + 8) * Ntot + ccol] = v1;
        }
    }
}

// ---------------------------------------------------------------------------
// Bt builders
// ---------------------------------------------------------------------------
__global__ void buildBtProj_kernel(const float* __restrict__ W, float* __restrict__ Bt)
{
    int idx = blockIdx.x * blockDim.x + threadIdx.x;
    if (idx >= 512 * 512) return;
    int c = idx >> 9;
    int f = idx & 511;
    int h = c >> 6;
    int d = c & 63;
    Bt[idx] = W[((size_t)h * 512 + f) * 64 + d];
}

__global__ void buildBtFus_kernel(const float* __restrict__ P, float* __restrict__ Bt)
{
    int idx = blockIdx.x * blockDim.x + threadIdx.x;
    if (idx >= 1024 * 1024) return;
    int n = idx >> 10;
    int k = idx & 1023;
    int pi = ((n >= 512) ? 2 : 0) + ((k >= 512) ? 1 : 0);
    Bt[idx] = P[((size_t)pi * 512 + (k & 511)) * 512 + (n & 511)];
}

__global__ void transposeAdj_kernel(const int* __restrict__ A, int* __restrict__ At,
                                    int N, int M)
{
    int idx = blockIdx.x * blockDim.x + threadIdx.x;
    int total = Bb * N * M;
    if (idx >= total) return;
    int b = idx / (N * M);
    int r = idx - b * (N * M);
    int m = r / N;
    int n = r - m * N;
    At[idx] = A[(size_t)b * N * M + (size_t)n * M + m];
}

// ---------------------------------------------------------------------------
// ehalf: out[b,h,n] = sum_d P[b,n, h*64+d] * avec[h*128 + off + d]
// ---------------------------------------------------------------------------
__global__ void ehalf_kernel(const float* __restrict__ P, const float* __restrict__ avec,
                             int off, float* __restrict__ out, int Nper)
{
    int row = blockIdx.x;
    int w = threadIdx.x >> 5;
    int lane = threadIdx.x & 31;
    int b = row / Nper;
    int n = row - b * Nper;
    const float* p = P + (size_t)row * 512 + w * 64;
    const float* a = avec + w * 128 + off;
    float s = p[lane] * a[lane] + p[lane + 32] * a[lane + 32];
#pragma unroll
    for (int o = 16; o > 0; o >>= 1) s += __shfl_down_sync(0xffffffffu, s, o);
    if (lane == 0) out[((size_t)(b * HH + w)) * Nper + n] = s;
}

// ---------------------------------------------------------------------------
// column stats for softmax over axis=2
// ---------------------------------------------------------------------------
__global__ __launch_bounds__(128) void colstats_kernel(
    const int* __restrict__ adjT, const float* __restrict__ eaN,
    const float* __restrict__ ebM, float* __restrict__ cmax,
    float* __restrict__ cinv, int Mdim, int NRED)
{
    int bm = blockIdx.x;
    int b = bm / Mdim;
    int m = bm - b * Mdim;
    const int* arow = adjT + (size_t)bm * NRED;
    int tid = threadIdx.x;
    int lane = tid & 31, w = tid >> 5;

    float ebv[8];
#pragma unroll
    for (int h = 0; h < 8; h++) ebv[h] = ebM[((size_t)(b * 8 + h)) * Mdim + m];

    float vmax[8];
#pragma unroll
    for (int h = 0; h < 8; h++) vmax[h] = NEGF;

    for (int n = tid; n < NRED; n += 128) {
        int adjv = arow[n];
#pragma unroll
        for (int h = 0; h < 8; h++) {
            float e = eaN[((size_t)(b * 8 + h)) * NRED + n] + ebv[h];
            e = (e >= 0.f) ? e : 0.2f * e;
            float v = (adjv > 0) ? e : NEGF;
            vmax[h] = fmaxf(vmax[h], v);
        }
    }

    __shared__ float red[8][4];
#pragma unroll
    for (int h = 0; h < 8; h++) {
        float v = vmax[h];
#pragma unroll
        for (int o = 16; o > 0; o >>= 1) v = fmaxf(v, __shfl_xor_sync(0xffffffffu, v, o));
        if (lane == 0) red[h][w] = v;
    }
    __syncthreads();
    float gmax[8];
#pragma unroll
    for (int h = 0; h < 8; h++)
        gmax[h] = fmaxf(fmaxf(red[h][0], red[h][1]), fmaxf(red[h][2], red[h][3]));
    __syncthreads();

    float vsum[8];
#pragma unroll
    for (int h = 0; h < 8; h++) vsum[h] = 0.f;
    for (int n = tid; n < NRED; n += 128) {
        int adjv = arow[n];
#pragma unroll
        for (int h = 0; h < 8; h++) {
            float e = eaN[((size_t)(b * 8 + h)) * NRED + n] + ebv[h];
            e = (e >= 0.f) ? e : 0.2f * e;
            float v = (adjv > 0) ? e : NEGF;
            vsum[h] += expf(v - gmax[h]);
        }
    }
#pragma unroll
    for (int h = 0; h < 8; h++) {
        float v = vsum[h];
#pragma unroll
        for (int o = 16; o > 0; o >>= 1) v += __shfl_xor_sync(0xffffffffu, v, o);
        if (lane == 0) red[h][w] = v;
    }
    __syncthreads();
    if (tid < 8) {
        int h = tid;
        float s = red[h][0] + red[h][1] + red[h][2] + red[h][3];
        cmax[((size_t)(b * 8 + h)) * Mdim + m] = gmax[h];
        cinv[((size_t)(b * 8 + h)) * Mdim + m] = 1.f / s;
    }
}

// ---------------------------------------------------------------------------
// Fused attention q2c
// ---------------------------------------------------------------------------
__global__ __launch_bounds__(256) void attn_q2c_kernel(
    const float* __restrict__ ea, const float* __restrict__ eb,
    const float* __restrict__ cmax, const float* __restrict__ cinv,
    const int* __restrict__ adj, const float* __restrict__ PQ,
    float* __restrict__ agg)
{
    extern __shared__ float sm[];
    float* eb_s = sm;
    float* cm_s = sm + 128;
    float* ci_s = sm + 256;
    float* ea_s = sm + 384;
    float* Wb_s = sm + 448;
    float* att_s = sm + 448 + 8192;

    int bh = blockIdx.y;
    int b = bh >> 3;
    int h = bh & 7;
    int n0 = blockIdx.x * 64;
    int tid = threadIdx.x;

    if (tid < 128) {
        eb_s[tid] = eb[(size_t)bh * 128 + tid];
        cm_s[tid] = cmax[(size_t)bh * 128 + tid];
        ci_s[tid] = cinv[(size_t)bh * 128 + tid];
    } else if (tid < 192) {
        ea_s[tid - 128] = ea[(size_t)bh * 1024 + n0 + (tid - 128)];
    }
    for (int idx = tid; idx < 128 * 64; idx += 256) {
        int m = idx >> 6, d = idx & 63;
        Wb_s[idx] = PQ[((size_t)(b * 128 + m)) * 512 + h * 64 + d];
    }
    __syncthreads();

    for (int idx = tid; idx < 64 * 128; idx += 256) {
        int m = idx & 127, n = idx >> 7;
        int adjv = adj[((size_t)(b * 1024 + n0 + n)) * 128 + m];
        float v = ea_s[n] + eb_s[m];
        v = (v >= 0.f) ? v : 0.2f * v;
        v = (adjv > 0) ? v : NEGF;
        att_s[m * 68 + n] = expf(v - cm_s[m]) * ci_s[m];
    }
    __syncthreads();

    int tn = tid & 15, tm = tid >> 4;
    int d0 = tn * 4, nl0 = tm * 4;
    float acc[4][4];
#pragma unroll
    for (int i = 0; i < 4; i++)
#pragma unroll
        for (int j = 0; j < 4; j++) acc[i][j] = 0.f;

    for (int k = 0; k < 128; k++) {
        float4 a4 = *(const float4*)&att_s[k * 68 + nl0];
        float4 b4 = *(const float4*)&Wb_s[k * 64 + d0];
        float a[4] = {a4.x, a4.y, a4.z, a4.w};
        float bb[4] = {b4.x, b4.y, b4.z, b4.w};
#pragma unroll
        for (int i = 0; i < 4; i++)
#pragma unroll
            for (int j = 0; j < 4; j++) acc[i][j] += a[i] * bb[j];
    }

#pragma unroll
    for (int i = 0; i < 4; i++) {
#pragma unroll
        for (int j = 0; j < 4; j++) {
            float v = acc[i][j];
            v = (v > 0.f) ? v : expm1f(v);
            agg[((size_t)(b * 1024 + n0 + nl0 + i)) * 512 + h * 64 + d0 + j] = v;
        }
    }
}

// ---------------------------------------------------------------------------
// Fused attention c2q
// ---------------------------------------------------------------------------
__global__ __launch_bounds__(256) void attn_c2q_kernel(
    const float* __restrict__ ea, const float* __restrict__ eb,
    const float* __restrict__ cmax, const float* __restrict__ cinv,
    const int* __restrict__ adj, const float* __restrict__ PC,
    float* __restrict__ agg)
{
    extern __shared__ float sm[];
    float* ea_s = sm;
    float* eb_s = sm + 128;
    float* cm_s = sm + 192;
    float* ci_s = sm + 256;
    float* Wb_s = sm + 320;
    float* att_s = sm + 320 + 4096;

    int bh = blockIdx.x;
    int b = bh >> 3;
    int h = bh & 7;
    int tid = threadIdx.x;

    if (tid < 128) ea_s[tid] = ea[(size_t)bh * 128 + tid];

    int tn = tid & 15, tm = tid >> 4;
    int d0 = tn * 4, nl0 = tm * 8;
    float acc[8][4];
#pragma unroll
    for (int i = 0; i < 8; i++)
#pragma unroll
        for (int j = 0; j < 4; j++) acc[i][j] = 0.f;

    for (int mt = 0; mt < 16; mt++) {
        int m0 = mt * 64;
        if (tid < 64) eb_s[tid] = eb[(size_t)bh * 1024 + m0 + tid];
        else if (tid < 128) cm_s[tid - 64] = cmax[(size_t)bh * 1024 + m0 + (tid - 64)];
        else if (tid < 192) ci_s[tid - 128] = cinv[(size_t)bh * 1024 + m0 + (tid - 128)];
        for (int idx = tid; idx < 64 * 64; idx += 256) {
            int m = idx >> 6, d = idx & 63;
            Wb_s[idx] = PC[((size_t)(b * 1024 + m0 + m)) * 512 + h * 64 + d];
        }
        __syncthreads();

        for (int idx = tid; idx < 128 * 64; idx += 256) {
            int m = idx & 63, n = idx >> 6;
            int adjv = adj[((size_t)(b * 128 + n)) * 1024 + m0 + m];
            float v = ea_s[n] + eb_s[m];
            v = (v >= 0.f) ? v : 0.2f * v;
            v = (adjv > 0) ? v : NEGF;
            att_s[m * 132 + n] = expf(v - cm_s[m]) * ci_s[m];
        }
        __syncthreads();

        for (int k = 0; k < 64; k++) {
            float4 b4 = *(const float4*)&Wb_s[k * 64 + d0];
            float4 a0 = *(const float4*)&att_s[k * 132 + nl0];
            float4 a1 = *(const float4*)&att_s[k * 132 + nl0 + 4];
            float a[8] = {a0.x, a0.y, a0.z, a0.w, a1.x, a1.y, a1.z, a1.w};
            float bb[4] = {b4.x, b4.y, b4.z, b4.w};
#pragma unroll
            for (int i = 0; i < 8; i++)
#pragma unroll
                for (int j = 0; j < 4; j++) acc[i][j] += a[i] * bb[j];
        }
        __syncthreads();
    }

#pragma unroll
    for (int i = 0; i < 8; i++) {
#pragma unroll
        for (int j = 0; j < 4; j++) {
            float v = acc[i][j];
            v = (v > 0.f) ? v : expm1f(v);
            agg[((size_t)(b * 128 + nl0 + i)) * 512 + h * 64 + d0 + j] = v;
        }
    }
}

// ---------------------------------------------------------------------------
// Fusion elementwise from NF[M,1024]
// ---------------------------------------------------------------------------
__global__ void fuse_ew_kernel(const float* __restrict__ a, const float* __restrict__ NF,
                               float* __restrict__ out, int n4)
{
    int i = blockIdx.x * blockDim.x + threadIdx.x;
    if (i >= n4) return;
    int row = i >> 7;
    int c = (i & 127) * 4;
    float4 av = *(const float4*)(a + (size_t)row * 512 + c);
    float4 nv = *(const float4*)(NF + (size_t)row * 1024 + c);
    float4 fv = *(const float4*)(NF + (size_t)row * 1024 + 512 + c);
    float4 o;
    { float s = 1.f / (1.f + expf(-fv.x)); o.x = s * nv.x + (1.f - s) * av.x; }
    { float s = 1.f / (1.f + expf(-fv.y)); o.y = s * nv.y + (1.f - s) * av.y; }
    { float s = 1.f / (1.f + expf(-fv.z)); o.z = s * nv.z + (1.f - s) * av.z; }
    { float s = 1.f / (1.f + expf(-fv.w)); o.w = s * nv.w + (1.f - s) * av.w; }
    *(float4*)(out + (size_t)row * 512 + c) = o;
}

// ---------------------------------------------------------------------------
// host side
// ---------------------------------------------------------------------------
static float* symf(const void* sym)
{
    void* p = nullptr;
    cudaGetSymbolAddress(&p, sym);
    return (float*)p;
}
static int* symi(const void* sym)
{
    void* p = nullptr;
    cudaGetSymbolAddress(&p, sym);
    return (int*)p;
}

static void gemm_tc(const float* A0, const float* A1, const float* B, float* C,
                    int M, int Ntot)
{
    int KS = A1 ? 32 : 16;
    dim3 grid(Ntot / 128, M / 128);
    mma_gemm_kernel<<<grid, 256>>>(A0, A1, B, C, Ntot, KS);
}

extern "C" void kernel_launch(void* const* d_in, const int* in_sizes, int n_in,
                              void* d_out, int out_size)
{
    const float* clip0 = (const float*)d_in[0];
    const float* quest0 = (const float*)d_in[1];
    const int* adj1 = (const int*)d_in[2];   // [B, Nc, Nq]
    const int* adj2 = (const int*)d_in[3];   // [B, Nq, Nc]
    const float* W_q2c = (const float*)d_in[4];
    const float* a_q2c = (const float*)d_in[5];
    const float* W_c2q = (const float*)d_in[6];
    const float* a_c2q = (const float*)d_in[7];
    const float* fus_q2c = (const float*)d_in[8];
    const float* fus_c2q = (const float*)d_in[9];

    float* out_clip = (float*)d_out;
    float* out_quest = out_clip + (size_t)Bb * NC * FD;

    float* pPC = symf(g_PC);
    float* pPQ = symf(g_PQ);
    float* pAgg = symf(g_agg);
    float* pNF = symf(g_NF);
    float* pClipA = symf(g_clipA);
    float* pQuestA = symf(g_questA);
    float* pEa = symf(g_ea);
    float* pEb = symf(g_eb);
    float* pCmax = symf(g_cmax);
    float* pCinv = symf(g_cinv);
    float* pWt = symf(g_Wt);
    float* pWt2 = symf(g_Wt2);
    float* pBtFus = symf(g_BtFus);
    int* pAdjT1 = symi(g_adjT1);
    int* pAdjT2 = symi(g_adjT2);

    const int SMEM_Q2C = (448 + 8192 + 128 * 68) * 4;
    const int SMEM_C2Q = (320 + 4096 + 64 * 132) * 4;
    cudaFuncSetAttribute(attn_q2c_kernel, cudaFuncAttributeMaxDynamicSharedMemorySize, SMEM_Q2C);
    cudaFuncSetAttribute(attn_c2q_kernel, cudaFuncAttributeMaxDynamicSharedMemorySize, SMEM_C2Q);

    {
        int tot1 = Bb * NC * NQ;
        transposeAdj_kernel<<<(tot1 + 255) / 256, 256>>>(adj1, pAdjT1, NC, NQ);
        transposeAdj_kernel<<<(tot1 + 255) / 256, 256>>>(adj2, pAdjT2, NQ, NC);
    }

    const size_t MCLIP = (size_t)Bb * NC;   // 65536
    const size_t MQ = (size_t)Bb * NQ;      // 8192

    const float* curC = clip0;
    const float* curQ = quest0;

    for (int l = 0; l < 2; l++) {
        float* clipNew = (l == 1) ? out_clip : pClipA;
        float* questNew = (l == 1) ? out_quest : pQuestA;
        const float* aq = a_q2c + (size_t)l * HH * 128;
        const float* ac = a_c2q + (size_t)l * HH * 128;

        buildBtProj_kernel<<<(512 * 512 + 255) / 256, 256>>>(
            W_q2c + (size_t)l * HH * FD * 64, pWt);
        buildBtProj_kernel<<<(512 * 512 + 255) / 256, 256>>>(
            W_c2q + (size_t)l * HH * FD * 64, pWt2);

        // ---------------- q2c GAT ----------------
        gemm_tc(curC, nullptr, pWt, pPC, (int)MCLIP, 512);
        gemm_tc(curQ, nullptr, pWt, pPQ, (int)MQ, 512);
        ehalf_kernel<<<(int)MCLIP, 256>>>(pPC, aq, 0, pEa, NC);
        ehalf_kernel<<<(int)MQ, 256>>>(pPQ, aq, 64, pEb, NQ);
        colstats_kernel<<<Bb * NQ, 128>>>(pAdjT1, pEa, pEb, pCmax, pCinv, NQ, NC);
        attn_q2c_kernel<<<dim3(NC / 64, Bb * HH), 256, SMEM_Q2C>>>(
            pEa, pEb, pCmax, pCinv, adj1, pPQ, pAgg);

        // ---------------- fusion (clip side) ----------------
        buildBtFus_kernel<<<(1024 * 1024 + 255) / 256, 256>>>(
            fus_q2c + (size_t)l * 4 * FD * FD, pBtFus);
        gemm_tc(curC, pAgg, pBtFus, pNF, (int)MCLIP, 1024);
        fuse_ew_kernel<<<(int)((MCLIP * 128 + 255) / 256), 256>>>(
            curC, pNF, clipNew, (int)(MCLIP * 128));

        // ---------------- c2q GAT (uses OLD clip) ----------------
        gemm_tc(curQ, nullptr, pWt2, pPQ, (int)MQ, 512);
        gemm_tc(curC, nullptr, pWt2, pPC, (int)MCLIP, 512);
        ehalf_kernel<<<(int)MQ, 256>>>(pPQ, ac, 0, pEa, NQ);
        ehalf_kernel<<<(int)MCLIP, 256>>>(pPC, ac, 64, pEb, NC);
        colstats_kernel<<<Bb * NC, 128>>>(pAdjT2, pEa, pEb, pCmax, pCinv, NC, NQ);
        attn_c2q_kernel<<<Bb * HH, 256, SMEM_C2Q>>>(
            pEa, pEb, pCmax, pCinv, adj2, pPC, pAgg);

        // ---------------- fusion (question side) ----------------
        buildBtFus_kernel<<<(1024 * 1024 + 255) / 256, 256>>>(
            fus_c2q + (size_t)l * 4 * FD * FD, pBtFus);
        gemm_tc(curQ, pAgg, pBtFus, pNF, (int)MQ, 1024);
        fuse_ew_kernel<<<(int)((MQ * 128 + 255) / 256), 256>>>(
            curQ, pNF, questNew, (int)(MQ * 128));

        curC = clipNew;
        curQ = questNew;
    }
    (void)in_sizes; (void)n_in; (void)out_size;
}

// round 7
// speedup vs baseline: 1.5713x; 1.0077x over previous
#include <cuda_runtime.h>
#include <cstdint>
#include <cstddef>

// ---------------------------------------------------------------------------
// CQEncoder: 2-layer bidirectional GAT + gated fusion.
// B=64, Nc=1024, Nq=128, F=NHID=512, H=8, DH=64, L=2
// Round 6 (= round 5 resubmit; container flake, kernel audited clean):
// dense GEMMs on mma.sync.m16n8k8 TF32 (baseline PTX ISA, compute_100-safe).
// ---------------------------------------------------------------------------

#define NEGF (-9e15f)

static const int Bb = 64;
static const int NC = 1024;
static const int NQ = 128;
static const int FD = 512;
static const int HH = 8;

// ------------------------- device scratch ----------------------------------
__device__ float g_PC[(size_t)64 * 1024 * 512];     // clip projection
__device__ float g_PQ[(size_t)64 * 128 * 512];      // question projection
__device__ float g_agg[(size_t)64 * 1024 * 512];    // q_agg / c_agg
__device__ float g_NF[(size_t)64 * 1024 * 1024];    // fusion output [M,1024]
__device__ float g_clipA[(size_t)64 * 1024 * 512];
__device__ float g_questA[(size_t)64 * 128 * 512];
__device__ float g_ea[(size_t)64 * 8 * 1024];
__device__ float g_eb[(size_t)64 * 8 * 1024];
__device__ float g_cmax[(size_t)64 * 8 * 1024];
__device__ float g_cinv[(size_t)64 * 8 * 1024];
__device__ float g_Wt[512 * 512];
__device__ float g_Wt2[512 * 512];
__device__ float g_BtFus[1024 * 1024];
__device__ int   g_adjT1[(size_t)64 * 128 * 1024];
__device__ int   g_adjT2[(size_t)64 * 1024 * 128];

__device__ __forceinline__ uint32_t cvt_tf32(float f)
{
    uint32_t r;
    asm("cvt.rna.tf32.f32 %0, %1;" : "=r"(r) : "f"(f));
    return r;
}

// ---------------------------------------------------------------------------
// TF32 mma.sync GEMM: C[M,Ntot] = [A0 | A1] @ Bm^T
//   A0/A1: [M,512] fp32 row-major (A1 used for K in [512,1024), may be null)
//   Bm:    [Ntot, KS*32] fp32 row-major (Bt layout: Bt[n,k])
//   Block tile 128x128, BK=32, 8 warps (2x4), warp tile 64x32 (4x4 m16n8k8).
//   Smem stride 36 -> conflict-free fragment loads. Reg-prefetch next k-tile.
// ---------------------------------------------------------------------------
__global__ __launch_bounds__(256) void mma_gemm_kernel(
    const float* __restrict__ A0, const float* __restrict__ A1,
    const float* __restrict__ Bm, float* __restrict__ C,
    int Ntot, int KS)
{
    __shared__ uint32_t As[128][36];
    __shared__ uint32_t Bs[128][36];

    const int tid = threadIdx.x;
    const int wid = tid >> 5;
    const int lane = tid & 31;
    const int n0 = blockIdx.x * 128;
    const int m0 = blockIdx.y * 128;
    const int wm = (wid >> 2) * 64;    // warp m offset: 0 or 64
    const int wn = (wid & 3) * 32;     // warp n offset: 0,32,64,96
    const int tg = lane >> 2;          // 0..7
    const int tr = lane & 3;           // 0..3

    const size_t ldb = (size_t)(KS * 32);

    float c[4][4][4];
#pragma unroll
    for (int mt = 0; mt < 4; mt++)
#pragma unroll
        for (int nt = 0; nt < 4; nt++)
#pragma unroll
            for (int j = 0; j < 4; j++) c[mt][nt][j] = 0.f;

    uint32_t ar[4][4], br[4][4];

    // ---- prefetch k-tile 0 into registers ----
    {
        const float* Ab = A0;
#pragma unroll
        for (int i = 0; i < 4; i++) {
            int f = tid + i * 256;
            int r = f >> 3, ck = (f & 7) << 2;
            float4 v = *(const float4*)(Ab + (size_t)(m0 + r) * 512 + ck);
            ar[i][0] = cvt_tf32(v.x); ar[i][1] = cvt_tf32(v.y);
            ar[i][2] = cvt_tf32(v.z); ar[i][3] = cvt_tf32(v.w);
            float4 w = *(const float4*)(Bm + (size_t)(n0 + r) * ldb + ck);
            br[i][0] = cvt_tf32(w.x); br[i][1] = cvt_tf32(w.y);
            br[i][2] = cvt_tf32(w.z); br[i][3] = cvt_tf32(w.w);
        }
    }

    for (int kt = 0; kt < KS; kt++) {
        // ---- store staged regs to smem ----
#pragma unroll
        for (int i = 0; i < 4; i++) {
            int f = tid + i * 256;
            int r = f >> 3, ck = (f & 7) << 2;
            As[r][ck + 0] = ar[i][0]; As[r][ck + 1] = ar[i][1];
            As[r][ck + 2] = ar[i][2]; As[r][ck + 3] = ar[i][3];
            Bs[r][ck + 0] = br[i][0]; Bs[r][ck + 1] = br[i][1];
            Bs[r][ck + 2] = br[i][2]; Bs[r][ck + 3] = br[i][3];
        }
        __syncthreads();

        // ---- prefetch next k-tile ----
        if (kt + 1 < KS) {
            const int k0 = (kt + 1) * 32;
            const float* Ab = (A1 && k0 >= 512) ? A1 : A0;
            const int ka = (A1 && k0 >= 512) ? k0 - 512 : k0;
#pragma unroll
            for (int i = 0; i < 4; i++) {
                int f = tid + i * 256;
                int r = f >> 3, ck = (f & 7) << 2;
                float4 v = *(const float4*)(Ab + (size_t)(m0 + r) * 512 + ka + ck);
                ar[i][0] = cvt_tf32(v.x); ar[i][1] = cvt_tf32(v.y);
                ar[i][2] = cvt_tf32(v.z); ar[i][3] = cvt_tf32(v.w);
                float4 w = *(const float4*)(Bm + (size_t)(n0 + r) * ldb + k0 + ck);
                br[i][0] = cvt_tf32(w.x); br[i][1] = cvt_tf32(w.y);
                br[i][2] = cvt_tf32(w.z); br[i][3] = cvt_tf32(w.w);
            }
        }

        // ---- compute 32-deep k with 4 x (m16n8k8) steps ----
#pragma unroll
        for (int kk = 0; kk < 32; kk += 8) {
            uint32_t a[4][4], b[4][2];
#pragma unroll
            for (int mt = 0; mt < 4; mt++) {
                int r0 = wm + mt * 16 + tg;
                a[mt][0] = As[r0][kk + tr];
                a[mt][1] = As[r0 + 8][kk + tr];
                a[mt][2] = As[r0][kk + tr + 4];
                a[mt][3] = As[r0 + 8][kk + tr + 4];
            }
#pragma unroll
            for (int nt = 0; nt < 4; nt++) {
                int r0 = wn + nt * 8 + tg;
                b[nt][0] = Bs[r0][kk + tr];
                b[nt][1] = Bs[r0][kk + tr + 4];
            }
#pragma unroll
            for (int mt = 0; mt < 4; mt++)
#pragma unroll
                for (int nt = 0; nt < 4; nt++) {
                    asm volatile(
                        "mma.sync.aligned.m16n8k8.row.col.f32.tf32.tf32.f32 "
                        "{%0,%1,%2,%3}, {%4,%5,%6,%7}, {%8,%9}, {%0,%1,%2,%3};"
                        : "+f"(c[mt][nt][0]), "+f"(c[mt][nt][1]),
                          "+f"(c[mt][nt][2]), "+f"(c[mt][nt][3])
                        : "r"(a[mt][0]), "r"(a[mt][1]), "r"(a[mt][2]), "r"(a[mt][3]),
                          "r"(b[nt][0]), "r"(b[nt][1]));
                }
        }
        __syncthreads();
    }

    // ---- epilogue ----
#pragma unroll
    for (int mt = 0; mt < 4; mt++) {
        int rrow = m0 + wm + mt * 16 + tg;
#pragma unroll
        for (int nt = 0; nt < 4; nt++) {
            int ccol = n0 + wn + nt * 8 + tr * 2;
            float2 v0 = make_float2(c[mt][nt][0], c[mt][nt][1]);
            float2 v1 = make_float2(c[mt][nt][2], c[mt][nt][3]);
            *(float2*)&C[(size_t)rrow * Ntot + ccol] = v0;
            *(float2*)&C[(size_t)(rrow + 8) * Ntot + ccol] = v1;
        }
    }
}

// ---------------------------------------------------------------------------
// Bt builders
// ---------------------------------------------------------------------------
__global__ void buildBtProj_kernel(const float* __restrict__ W, float* __restrict__ Bt)
{
    int idx = blockIdx.x * blockDim.x + threadIdx.x;
    if (idx >= 512 * 512) return;
    int c = idx >> 9;
    int f = idx & 511;
    int h = c >> 6;
    int d = c & 63;
    Bt[idx] = W[((size_t)h * 512 + f) * 64 + d];
}

__global__ void buildBtFus_kernel(const float* __restrict__ P, float* __restrict__ Bt)
{
    int idx = blockIdx.x * blockDim.x + threadIdx.x;
    if (idx >= 1024 * 1024) return;
    int n = idx >> 10;
    int k = idx & 1023;
    int pi = ((n >= 512) ? 2 : 0) + ((k >= 512) ? 1 : 0);
    Bt[idx] = P[((size_t)pi * 512 + (k & 511)) * 512 + (n & 511)];
}

__global__ void transposeAdj_kernel(const int* __restrict__ A, int* __restrict__ At,
                                    int N, int M)
{
    int idx = blockIdx.x * blockDim.x + threadIdx.x;
    int total = Bb * N * M;
    if (idx >= total) return;
    int b = idx / (N * M);
    int r = idx - b * (N * M);
    int m = r / N;
    int n = r - m * N;
    At[idx] = A[(size_t)b * N * M + (size_t)n * M + m];
}

// ---------------------------------------------------------------------------
// ehalf: out[b,h,n] = sum_d P[b,n, h*64+d] * avec[h*128 + off + d]
// ---------------------------------------------------------------------------
__global__ void ehalf_kernel(const float* __restrict__ P, const float* __restrict__ avec,
                             int off, float* __restrict__ out, int Nper)
{
    int row = blockIdx.x;
    int w = threadIdx.x >> 5;
    int lane = threadIdx.x & 31;
    int b = row / Nper;
    int n = row - b * Nper;
    const float* p = P + (size_t)row * 512 + w * 64;
    const float* a = avec + w * 128 + off;
    float s = p[lane] * a[lane] + p[lane + 32] * a[lane + 32];
#pragma unroll
    for (int o = 16; o > 0; o >>= 1) s += __shfl_down_sync(0xffffffffu, s, o);
    if (lane == 0) out[((size_t)(b * HH + w)) * Nper + n] = s;
}

// ---------------------------------------------------------------------------
// column stats for softmax over axis=2
// ---------------------------------------------------------------------------
__global__ __launch_bounds__(128) void colstats_kernel(
    const int* __restrict__ adjT, const float* __restrict__ eaN,
    const float* __restrict__ ebM, float* __restrict__ cmax,
    float* __restrict__ cinv, int Mdim, int NRED)
{
    int bm = blockIdx.x;
    int b = bm / Mdim;
    int m = bm - b * Mdim;
    const int* arow = adjT + (size_t)bm * NRED;
    int tid = threadIdx.x;
    int lane = tid & 31, w = tid >> 5;

    float ebv[8];
#pragma unroll
    for (int h = 0; h < 8; h++) ebv[h] = ebM[((size_t)(b * 8 + h)) * Mdim + m];

    float vmax[8];
#pragma unroll
    for (int h = 0; h < 8; h++) vmax[h] = NEGF;

    for (int n = tid; n < NRED; n += 128) {
        int adjv = arow[n];
#pragma unroll
        for (int h = 0; h < 8; h++) {
            float e = eaN[((size_t)(b * 8 + h)) * NRED + n] + ebv[h];
            e = (e >= 0.f) ? e : 0.2f * e;
            float v = (adjv > 0) ? e : NEGF;
            vmax[h] = fmaxf(vmax[h], v);
        }
    }

    __shared__ float red[8][4];
#pragma unroll
    for (int h = 0; h < 8; h++) {
        float v = vmax[h];
#pragma unroll
        for (int o = 16; o > 0; o >>= 1) v = fmaxf(v, __shfl_xor_sync(0xffffffffu, v, o));
        if (lane == 0) red[h][w] = v;
    }
    __syncthreads();
    float gmax[8];
#pragma unroll
    for (int h = 0; h < 8; h++)
        gmax[h] = fmaxf(fmaxf(red[h][0], red[h][1]), fmaxf(red[h][2], red[h][3]));
    __syncthreads();

    float vsum[8];
#pragma unroll
    for (int h = 0; h < 8; h++) vsum[h] = 0.f;
    for (int n = tid; n < NRED; n += 128) {
        int adjv = arow[n];
#pragma unroll
        for (int h = 0; h < 8; h++) {
            float e = eaN[((size_t)(b * 8 + h)) * NRED + n] + ebv[h];
            e = (e >= 0.f) ? e : 0.2f * e;
            float v = (adjv > 0) ? e : NEGF;
            vsum[h] += expf(v - gmax[h]);
        }
    }
#pragma unroll
    for (int h = 0; h < 8; h++) {
        float v = vsum[h];
#pragma unroll
        for (int o = 16; o > 0; o >>= 1) v += __shfl_xor_sync(0xffffffffu, v, o);
        if (lane == 0) red[h][w] = v;
    }
    __syncthreads();
    if (tid < 8) {
        int h = tid;
        float s = red[h][0] + red[h][1] + red[h][2] + red[h][3];
        cmax[((size_t)(b * 8 + h)) * Mdim + m] = gmax[h];
        cinv[((size_t)(b * 8 + h)) * Mdim + m] = 1.f / s;
    }
}

// ---------------------------------------------------------------------------
// Fused attention q2c
// ---------------------------------------------------------------------------
__global__ __launch_bounds__(256) void attn_q2c_kernel(
    const float* __restrict__ ea, const float* __restrict__ eb,
    const float* __restrict__ cmax, const float* __restrict__ cinv,
    const int* __restrict__ adj, const float* __restrict__ PQ,
    float* __restrict__ agg)
{
    extern __shared__ float sm[];
    float* eb_s = sm;
    float* cm_s = sm + 128;
    float* ci_s = sm + 256;
    float* ea_s = sm + 384;
    float* Wb_s = sm + 448;
    float* att_s = sm + 448 + 8192;

    int bh = blockIdx.y;
    int b = bh >> 3;
    int h = bh & 7;
    int n0 = blockIdx.x * 64;
    int tid = threadIdx.x;

    if (tid < 128) {
        eb_s[tid] = eb[(size_t)bh * 128 + tid];
        cm_s[tid] = cmax[(size_t)bh * 128 + tid];
        ci_s[tid] = cinv[(size_t)bh * 128 + tid];
    } else if (tid < 192) {
        ea_s[tid - 128] = ea[(size_t)bh * 1024 + n0 + (tid - 128)];
    }
    for (int idx = tid; idx < 128 * 64; idx += 256) {
        int m = idx >> 6, d = idx & 63;
        Wb_s[idx] = PQ[((size_t)(b * 128 + m)) * 512 + h * 64 + d];
    }
    __syncthreads();

    for (int idx = tid; idx < 64 * 128; idx += 256) {
        int m = idx & 127, n = idx >> 7;
        int adjv = adj[((size_t)(b * 1024 + n0 + n)) * 128 + m];
        float v = ea_s[n] + eb_s[m];
        v = (v >= 0.f) ? v : 0.2f * v;
        v = (adjv > 0) ? v : NEGF;
        att_s[m * 68 + n] = expf(v - cm_s[m]) * ci_s[m];
    }
    __syncthreads();

    int tn = tid & 15, tm = tid >> 4;
    int d0 = tn * 4, nl0 = tm * 4;
    float acc[4][4];
#pragma unroll
    for (int i = 0; i < 4; i++)
#pragma unroll
        for (int j = 0; j < 4; j++) acc[i][j] = 0.f;

    for (int k = 0; k < 128; k++) {
        float4 a4 = *(const float4*)&att_s[k * 68 + nl0];
        float4 b4 = *(const float4*)&Wb_s[k * 64 + d0];
        float a[4] = {a4.x, a4.y, a4.z, a4.w};
        float bb[4] = {b4.x, b4.y, b4.z, b4.w};
#pragma unroll
        for (int i = 0; i < 4; i++)
#pragma unroll
            for (int j = 0; j < 4; j++) acc[i][j] += a[i] * bb[j];
    }

#pragma unroll
    for (int i = 0; i < 4; i++) {
#pragma unroll
        for (int j = 0; j < 4; j++) {
            float v = acc[i][j];
            v = (v > 0.f) ? v : expm1f(v);
            agg[((size_t)(b * 1024 + n0 + nl0 + i)) * 512 + h * 64 + d0 + j] = v;
        }
    }
}

// ---------------------------------------------------------------------------
// Fused attention c2q
// ---------------------------------------------------------------------------
__global__ __launch_bounds__(256) void attn_c2q_kernel(
    const float* __restrict__ ea, const float* __restrict__ eb,
    const float* __restrict__ cmax, const float* __restrict__ cinv,
    const int* __restrict__ adj, const float* __restrict__ PC,
    float* __restrict__ agg)
{
    extern __shared__ float sm[];
    float* ea_s = sm;
    float* eb_s = sm + 128;
    float* cm_s = sm + 192;
    float* ci_s = sm + 256;
    float* Wb_s = sm + 320;
    float* att_s = sm + 320 + 4096;

    int bh = blockIdx.x;
    int b = bh >> 3;
    int h = bh & 7;
    int tid = threadIdx.x;

    if (tid < 128) ea_s[tid] = ea[(size_t)bh * 128 + tid];

    int tn = tid & 15, tm = tid >> 4;
    int d0 = tn * 4, nl0 = tm * 8;
    float acc[8][4];
#pragma unroll
    for (int i = 0; i < 8; i++)
#pragma unroll
        for (int j = 0; j < 4; j++) acc[i][j] = 0.f;

    for (int mt = 0; mt < 16; mt++) {
        int m0 = mt * 64;
        if (tid < 64) eb_s[tid] = eb[(size_t)bh * 1024 + m0 + tid];
        else if (tid < 128) cm_s[tid - 64] = cmax[(size_t)bh * 1024 + m0 + (tid - 64)];
        else if (tid < 192) ci_s[tid - 128] = cinv[(size_t)bh * 1024 + m0 + (tid - 128)];
        for (int idx = tid; idx < 64 * 64; idx += 256) {
            int m = idx >> 6, d = idx & 63;
            Wb_s[idx] = PC[((size_t)(b * 1024 + m0 + m)) * 512 + h * 64 + d];
        }
        __syncthreads();

        for (int idx = tid; idx < 128 * 64; idx += 256) {
            int m = idx & 63, n = idx >> 6;
            int adjv = adj[((size_t)(b * 128 + n)) * 1024 + m0 + m];
            float v = ea_s[n] + eb_s[m];
            v = (v >= 0.f) ? v : 0.2f * v;
            v = (adjv > 0) ? v : NEGF;
            att_s[m * 132 + n] = expf(v - cm_s[m]) * ci_s[m];
        }
        __syncthreads();

        for (int k = 0; k < 64; k++) {
            float4 b4 = *(const float4*)&Wb_s[k * 64 + d0];
            float4 a0 = *(const float4*)&att_s[k * 132 + nl0];
            float4 a1 = *(const float4*)&att_s[k * 132 + nl0 + 4];
            float a[8] = {a0.x, a0.y, a0.z, a0.w, a1.x, a1.y, a1.z, a1.w};
            float bb[4] = {b4.x, b4.y, b4.z, b4.w};
#pragma unroll
            for (int i = 0; i < 8; i++)
#pragma unroll
                for (int j = 0; j < 4; j++) acc[i][j] += a[i] * bb[j];
        }
        __syncthreads();
    }

#pragma unroll
    for (int i = 0; i < 8; i++) {
#pragma unroll
        for (int j = 0; j < 4; j++) {
            float v = acc[i][j];
            v = (v > 0.f) ? v : expm1f(v);
            agg[((size_t)(b * 128 + nl0 + i)) * 512 + h * 64 + d0 + j] = v;
        }
    }
}

// ---------------------------------------------------------------------------
// Fusion elementwise from NF[M,1024]
// ---------------------------------------------------------------------------
__global__ void fuse_ew_kernel(const float* __restrict__ a, const float* __restrict__ NF,
                               float* __restrict__ out, int n4)
{
    int i = blockIdx.x * blockDim.x + threadIdx.x;
    if (i >= n4) return;
    int row = i >> 7;
    int c = (i & 127) * 4;
    float4 av = *(const float4*)(a + (size_t)row * 512 + c);
    float4 nv = *(const float4*)(NF + (size_t)row * 1024 + c);
    float4 fv = *(const float4*)(NF + (size_t)row * 1024 + 512 + c);
    float4 o;
    { float s = 1.f / (1.f + expf(-fv.x)); o.x = s * nv.x + (1.f - s) * av.x; }
    { float s = 1.f / (1.f + expf(-fv.y)); o.y = s * nv.y + (1.f - s) * av.y; }
    { float s = 1.f / (1.f + expf(-fv.z)); o.z = s * nv.z + (1.f - s) * av.z; }
    { float s = 1.f / (1.f + expf(-fv.w)); o.w = s * nv.w + (1.f - s) * av.w; }
    *(float4*)(out + (size_t)row * 512 + c) = o;
}

// ---------------------------------------------------------------------------
// host side
// ---------------------------------------------------------------------------
static float* symf(const void* sym)
{
    void* p = nullptr;
    cudaGetSymbolAddress(&p, sym);
    return (float*)p;
}
static int* symi(const void* sym)
{
    void* p = nullptr;
    cudaGetSymbolAddress(&p, sym);
    return (int*)p;
}

static void gemm_tc(const float* A0, const float* A1, const float* B, float* C,
                    int M, int Ntot)
{
    int KS = A1 ? 32 : 16;
    dim3 grid(Ntot / 128, M / 128);
    mma_gemm_kernel<<<grid, 256>>>(A0, A1, B, C, Ntot, KS);
}

extern "C" void kernel_launch(void* const* d_in, const int* in_sizes, int n_in,
                              void* d_out, int out_size)
{
    const float* clip0 = (const float*)d_in[0];
    const float* quest0 = (const float*)d_in[1];
    const int* adj1 = (const int*)d_in[2];   // [B, Nc, Nq]
    const int* adj2 = (const int*)d_in[3];   // [B, Nq, Nc]
    const float* W_q2c = (const float*)d_in[4];
    const float* a_q2c = (const float*)d_in[5];
    const float* W_c2q = (const float*)d_in[6];
    const float* a_c2q = (const float*)d_in[7];
    const float* fus_q2c = (const float*)d_in[8];
    const float* fus_c2q = (const float*)d_in[9];

    float* out_clip = (float*)d_out;
    float* out_quest = out_clip + (size_t)Bb * NC * FD;

    float* pPC = symf(g_PC);
    float* pPQ = symf(g_PQ);
    float* pAgg = symf(g_agg);
    float* pNF = symf(g_NF);
    float* pClipA = symf(g_clipA);
    float* pQuestA = symf(g_questA);
    float* pEa = symf(g_ea);
    float* pEb = symf(g_eb);
    float* pCmax = symf(g_cmax);
    float* pCinv = symf(g_cinv);
    float* pWt = symf(g_Wt);
    float* pWt2 = symf(g_Wt2);
    float* pBtFus = symf(g_BtFus);
    int* pAdjT1 = symi(g_adjT1);
    int* pAdjT2 = symi(g_adjT2);

    const int SMEM_Q2C = (448 + 8192 + 128 * 68) * 4;
    const int SMEM_C2Q = (320 + 4096 + 64 * 132) * 4;
    cudaFuncSetAttribute(attn_q2c_kernel, cudaFuncAttributeMaxDynamicSharedMemorySize, SMEM_Q2C);
    cudaFuncSetAttribute(attn_c2q_kernel, cudaFuncAttributeMaxDynamicSharedMemorySize, SMEM_C2Q);

    {
        int tot1 = Bb * NC * NQ;
        transposeAdj_kernel<<<(tot1 + 255) / 256, 256>>>(adj1, pAdjT1, NC, NQ);
        transposeAdj_kernel<<<(tot1 + 255) / 256, 256>>>(adj2, pAdjT2, NQ, NC);
    }

    const size_t MCLIP = (size_t)Bb * NC;   // 65536
    const size_t MQ = (size_t)Bb * NQ;      // 8192

    const float* curC = clip0;
    const float* curQ = quest0;

    for (int l = 0; l < 2; l++) {
        float* clipNew = (l == 1) ? out_clip : pClipA;
        float* questNew = (l == 1) ? out_quest : pQuestA;
        const float* aq = a_q2c + (size_t)l * HH * 128;
        const float* ac = a_c2q + (size_t)l * HH * 128;

        buildBtProj_kernel<<<(512 * 512 + 255) / 256, 256>>>(
            W_q2c + (size_t)l * HH * FD * 64, pWt);
        buildBtProj_kernel<<<(512 * 512 + 255) / 256, 256>>>(
            W_c2q + (size_t)l * HH * FD * 64, pWt2);

        // ---------------- q2c GAT ----------------
        gemm_tc(curC, nullptr, pWt, pPC, (int)MCLIP, 512);
        gemm_tc(curQ, nullptr, pWt, pPQ, (int)MQ, 512);
        ehalf_kernel<<<(int)MCLIP, 256>>>(pPC, aq, 0, pEa, NC);
        ehalf_kernel<<<(int)MQ, 256>>>(pPQ, aq, 64, pEb, NQ);
        colstats_kernel<<<Bb * NQ, 128>>>(pAdjT1, pEa, pEb, pCmax, pCinv, NQ, NC);
        attn_q2c_kernel<<<dim3(NC / 64, Bb * HH), 256, SMEM_Q2C>>>(
            pEa, pEb, pCmax, pCinv, adj1, pPQ, pAgg);

        // ---------------- fusion (clip side) ----------------
        buildBtFus_kernel<<<(1024 * 1024 + 255) / 256, 256>>>(
            fus_q2c + (size_t)l * 4 * FD * FD, pBtFus);
        gemm_tc(curC, pAgg, pBtFus, pNF, (int)MCLIP, 1024);
        fuse_ew_kernel<<<(int)((MCLIP * 128 + 255) / 256), 256>>>(
            curC, pNF, clipNew, (int)(MCLIP * 128));

        // ---------------- c2q GAT (uses OLD clip) ----------------
        gemm_tc(curQ, nullptr, pWt2, pPQ, (int)MQ, 512);
        gemm_tc(curC, nullptr, pWt2, pPC, (int)MCLIP, 512);
        ehalf_kernel<<<(int)MQ, 256>>>(pPQ, ac, 0, pEa, NQ);
        ehalf_kernel<<<(int)MCLIP, 256>>>(pPC, ac, 64, pEb, NC);
        colstats_kernel<<<Bb * NC, 128>>>(pAdjT2, pEa, pEb, pCmax, pCinv, NC, NQ);
        attn_c2q_kernel<<<Bb * HH, 256, SMEM_C2Q>>>(
            pEa, pEb, pCmax, pCinv, adj2, pPC, pAgg);

        // ---------------- fusion (question side) ----------------
        buildBtFus_kernel<<<(1024 * 1024 + 255) / 256, 256>>>(
            fus_c2q + (size_t)l * 4 * FD * FD, pBtFus);
        gemm_tc(curQ, pAgg, pBtFus, pNF, (int)MQ, 1024);
        fuse_ew_kernel<<<(int)((MQ * 128 + 255) / 256), 256>>>(
            curQ, pNF, questNew, (int)(MQ * 128));

        curC = clipNew;
        curQ = questNew;
    }
    (void)in_sizes; (void)n_in; (void)out_size;
}